// round 2
// baseline (speedup 1.0000x reference)
#include <cuda_runtime.h>

// Fused sRGB->CIELab + per-image L min-max normalization.
// Input : x  [512, 128, 128, 3] fp32 sRGB in [0,1]
// Output: out[512, 128, 128, 3] fp32 = { (L-Lmin)/(Lmax-Lmin), (a+128)/255, (b+128)/255 }
//
// One CTA per image. Phase 1: float4 loads, compute Lab, write ab, stash L in
// smem, track min/max. Reduce. Phase 2: write normalized L.
// Transcendentals forced onto MUFU via inline PTX lg2/ex2.approx.

#define NPIX    16384     // 128*128
#define THREADS 512
#define GROUPS  (NPIX / (THREADS * 4))   // 8 groups of 4 pixels per thread

__device__ __forceinline__ float mufu_lg2(float x) {
    float r;
    asm("lg2.approx.f32 %0, %1;" : "=f"(r) : "f"(x));
    return r;
}
__device__ __forceinline__ float mufu_ex2(float x) {
    float r;
    asm("ex2.approx.f32 %0, %1;" : "=f"(r) : "f"(x));
    return r;
}

__device__ __forceinline__ float srgb_lin(float c) {
    // ((c + 0.055)/1.055)^2.4 if c > 0.04045 else c/12.92
    float t = fmaf(c, 1.0f / 1.055f, 0.055f / 1.055f);
    float p = mufu_ex2(2.4f * mufu_lg2(t));
    return (c > 0.04045f) ? p : c * (1.0f / 12.92f);
}

__device__ __forceinline__ float xyz_f(float t) {
    // cbrt(t) if t > 0.008856 else 7.787t + 16/116
    float cr = mufu_ex2((1.0f / 3.0f) * mufu_lg2(t));
    return (t > 0.008856f) ? cr : fmaf(t, 7.787f, 16.0f / 116.0f);
}

__device__ __forceinline__ void lab_pixel(float r, float g, float b,
                                          float& L, float& a01, float& b01) {
    float rl = srgb_lin(r);
    float gl = srgb_lin(g);
    float bl = srgb_lin(b);
    // RGB->XYZ with D65 white division folded into the matrix
    const float M00 = 0.412453f / 0.95047f, M01 = 0.357580f / 0.95047f, M02 = 0.180423f / 0.95047f;
    const float M10 = 0.212671f,            M11 = 0.715160f,            M12 = 0.072169f;
    const float M20 = 0.019334f / 1.08883f, M21 = 0.119193f / 1.08883f, M22 = 0.950227f / 1.08883f;
    float X = fmaf(M00, rl, fmaf(M01, gl, M02 * bl));
    float Y = fmaf(M10, rl, fmaf(M11, gl, M12 * bl));
    float Z = fmaf(M20, rl, fmaf(M21, gl, M22 * bl));
    float fx = xyz_f(X);
    float fy = xyz_f(Y);
    float fz = xyz_f(Z);
    L   = fmaf(116.0f, fy, -16.0f);
    a01 = fmaf(fx - fy, 500.0f / 255.0f, 128.0f / 255.0f);
    b01 = fmaf(fy - fz, 200.0f / 255.0f, 128.0f / 255.0f);
}

__global__ void __launch_bounds__(THREADS, 2)
rgb2lab_norm_kernel(const float* __restrict__ x, float* __restrict__ out) {
    extern __shared__ float smem[];
    float* sL  = smem;           // [16384] L values
    float* red = smem + NPIX;    // [64] reduction scratch

    const int b   = blockIdx.x;
    const int tid = threadIdx.x;

    const float4* in4 = (const float4*)(x + (size_t)b * NPIX * 3);
    float*        o   = out + (size_t)b * NPIX * 3;

    float lmin =  3.402823466e38f;
    float lmax = -3.402823466e38f;

    // ---------------- phase 1: compute Lab, write ab, stash L ----------------
    #pragma unroll 2
    for (int j = 0; j < GROUPS; j++) {
        int gidx = tid + j * THREADS;           // group of 4 consecutive pixels
        float4 v0 = in4[(size_t)gidx * 3 + 0];
        float4 v1 = in4[(size_t)gidx * 3 + 1];
        float4 v2 = in4[(size_t)gidx * 3 + 2];
        int p0 = gidx * 4;

        float L, a01, b01;

        lab_pixel(v0.x, v0.y, v0.z, L, a01, b01);
        o[(size_t)p0 * 3 + 1] = a01;  o[(size_t)p0 * 3 + 2] = b01;
        sL[p0] = L;  lmin = fminf(lmin, L);  lmax = fmaxf(lmax, L);

        lab_pixel(v0.w, v1.x, v1.y, L, a01, b01);
        o[(size_t)(p0 + 1) * 3 + 1] = a01;  o[(size_t)(p0 + 1) * 3 + 2] = b01;
        sL[p0 + 1] = L;  lmin = fminf(lmin, L);  lmax = fmaxf(lmax, L);

        lab_pixel(v1.z, v1.w, v2.x, L, a01, b01);
        o[(size_t)(p0 + 2) * 3 + 1] = a01;  o[(size_t)(p0 + 2) * 3 + 2] = b01;
        sL[p0 + 2] = L;  lmin = fminf(lmin, L);  lmax = fmaxf(lmax, L);

        lab_pixel(v2.y, v2.z, v2.w, L, a01, b01);
        o[(size_t)(p0 + 3) * 3 + 1] = a01;  o[(size_t)(p0 + 3) * 3 + 2] = b01;
        sL[p0 + 3] = L;  lmin = fminf(lmin, L);  lmax = fmaxf(lmax, L);
    }

    // ---------------- min/max reduction over the image ----------------
    #pragma unroll
    for (int off = 16; off > 0; off >>= 1) {
        lmin = fminf(lmin, __shfl_xor_sync(0xffffffffu, lmin, off));
        lmax = fmaxf(lmax, __shfl_xor_sync(0xffffffffu, lmax, off));
    }
    int lane = tid & 31, wid = tid >> 5;
    if (lane == 0) { red[wid] = lmin; red[16 + wid] = lmax; }
    __syncthreads();
    if (tid == 0) {
        float mn = red[0], mx = red[16];
        #pragma unroll
        for (int i = 1; i < 16; i++) {
            mn = fminf(mn, red[i]);
            mx = fmaxf(mx, red[16 + i]);
        }
        red[32] = mn;
        red[33] = 1.0f / (mx - mn);
    }
    __syncthreads();
    const float Lmin = red[32];
    const float sc   = red[33];

    // ---------------- phase 2: write normalized L ----------------
    #pragma unroll
    for (int j = 0; j < GROUPS; j++) {
        int gidx = tid + j * THREADS;
        float4 lv = ((const float4*)sL)[gidx];
        int p0 = gidx * 4;
        o[(size_t)p0 * 3]       = (lv.x - Lmin) * sc;
        o[(size_t)(p0 + 1) * 3] = (lv.y - Lmin) * sc;
        o[(size_t)(p0 + 2) * 3] = (lv.z - Lmin) * sc;
        o[(size_t)(p0 + 3) * 3] = (lv.w - Lmin) * sc;
    }
}

extern "C" void kernel_launch(void* const* d_in, const int* in_sizes, int n_in,
                              void* d_out, int out_size) {
    const float* x   = (const float*)d_in[0];
    float*       out = (float*)d_out;

    const int smem_bytes = (NPIX + 64) * sizeof(float);  // 65792 B
    cudaFuncSetAttribute(rgb2lab_norm_kernel,
                         cudaFuncAttributeMaxDynamicSharedMemorySize, smem_bytes);

    const int n_images = 512;  // out_size / (128*128*3)
    rgb2lab_norm_kernel<<<n_images, THREADS, smem_bytes>>>(x, out);
}

// round 3
// speedup vs baseline: 2.1965x; 2.1965x over previous
#include <cuda_runtime.h>
#include <float.h>

// Fused sRGB->CIELab + per-image L min-max normalization, two-kernel version.
//
// K1: per-image Y min/max (L is monotonic in Y, so reducing Y suffices).
//     4 CTAs per image write partials to __device__ scratch. 6 MUFU/px.
// K2: full Lab conversion + normalization, fully coalesced float4 stores.
//     Images processed in reverse order to exploit K1's L2 residue.

#define NPIX      16384            // 128*128
#define NIMG      512
#define K1_SUBS   4                // CTAs per image in K1
#define K2_SUBS   8                // CTAs per image in K2
#define THREADS   256
#define K1_PX     (NPIX / K1_SUBS)         // 4096 px per K1 CTA
#define K2_PX     (NPIX / K2_SUBS)         // 2048 px per K2 CTA
#define K1_GROUPS (K1_PX / (THREADS * 4))  // 4 groups of 4 px per thread
#define K2_GROUPS (K2_PX / (THREADS * 4))  // 2 groups of 4 px per thread

__device__ float g_pmin[NIMG * K1_SUBS];
__device__ float g_pmax[NIMG * K1_SUBS];

__device__ __forceinline__ float mufu_lg2(float x) {
    float r; asm("lg2.approx.f32 %0, %1;" : "=f"(r) : "f"(x)); return r;
}
__device__ __forceinline__ float mufu_ex2(float x) {
    float r; asm("ex2.approx.f32 %0, %1;" : "=f"(r) : "f"(x)); return r;
}
__device__ __forceinline__ float mufu_rcp(float x) {
    float r; asm("rcp.approx.f32 %0, %1;" : "=f"(r) : "f"(x)); return r;
}

__device__ __forceinline__ float srgb_lin(float c) {
    // ((c + 0.055)/1.055)^2.4 if c > 0.04045 else c/12.92
    float t = fmaf(c, 1.0f / 1.055f, 0.055f / 1.055f);
    float p = mufu_ex2(2.4f * mufu_lg2(t));
    return (c > 0.04045f) ? p : c * (1.0f / 12.92f);
}

__device__ __forceinline__ float xyz_f(float t) {
    // cbrt(t) if t > 0.008856 else 7.787t + 16/116  (monotonic, continuous)
    float cr = mufu_ex2((1.0f / 3.0f) * mufu_lg2(t));
    return (t > 0.008856f) ? cr : fmaf(t, 7.787f, 16.0f / 116.0f);
}

// Y (CIE luminance, white=1 for Y channel) from sRGB
__device__ __forceinline__ float lum_Y(float r, float g, float b) {
    float rl = srgb_lin(r), gl = srgb_lin(g), bl = srgb_lin(b);
    return fmaf(0.212671f, rl, fmaf(0.715160f, gl, 0.072169f * bl));
}

// ---------------------------------------------------------------- K1
__global__ void __launch_bounds__(THREADS)
minmax_kernel(const float* __restrict__ x) {
    __shared__ float red[16];
    const int bid = blockIdx.x;                 // 0 .. NIMG*K1_SUBS-1
    const int img = bid >> 2, sub = bid & 3;
    const int tid = threadIdx.x;

    const float4* in4 = (const float4*)(x + (size_t)img * NPIX * 3)
                      + (size_t)sub * (K1_PX * 3 / 4);

    float ymin = FLT_MAX, ymax = -FLT_MAX;

    #pragma unroll
    for (int j = 0; j < K1_GROUPS; j++) {
        int gi = tid + j * THREADS;             // group of 4 pixels
        float4 v0 = in4[(size_t)gi * 3 + 0];
        float4 v1 = in4[(size_t)gi * 3 + 1];
        float4 v2 = in4[(size_t)gi * 3 + 2];
        float y0 = lum_Y(v0.x, v0.y, v0.z);
        float y1 = lum_Y(v0.w, v1.x, v1.y);
        float y2 = lum_Y(v1.z, v1.w, v2.x);
        float y3 = lum_Y(v2.y, v2.z, v2.w);
        ymin = fminf(fminf(fminf(ymin, y0), fminf(y1, y2)), y3);
        ymax = fmaxf(fmaxf(fmaxf(ymax, y0), fmaxf(y1, y2)), y3);
    }

    #pragma unroll
    for (int off = 16; off > 0; off >>= 1) {
        ymin = fminf(ymin, __shfl_xor_sync(0xffffffffu, ymin, off));
        ymax = fmaxf(ymax, __shfl_xor_sync(0xffffffffu, ymax, off));
    }
    int lane = tid & 31, wid = tid >> 5;
    if (lane == 0) { red[wid] = ymin; red[8 + wid] = ymax; }
    __syncthreads();
    if (tid == 0) {
        float mn = red[0], mx = red[8];
        #pragma unroll
        for (int i = 1; i < 8; i++) {
            mn = fminf(mn, red[i]);
            mx = fmaxf(mx, red[8 + i]);
        }
        g_pmin[bid] = mn;
        g_pmax[bid] = mx;
    }
}

// ---------------------------------------------------------------- K2
__device__ __forceinline__ void lab_pixel(float r, float g, float b,
                                          float fmin, float sf,
                                          float& L01, float& a01, float& b01) {
    float rl = srgb_lin(r);
    float gl = srgb_lin(g);
    float bl = srgb_lin(b);
    const float M00 = 0.412453f / 0.95047f, M01 = 0.357580f / 0.95047f, M02 = 0.180423f / 0.95047f;
    const float M10 = 0.212671f,            M11 = 0.715160f,            M12 = 0.072169f;
    const float M20 = 0.019334f / 1.08883f, M21 = 0.119193f / 1.08883f, M22 = 0.950227f / 1.08883f;
    float X = fmaf(M00, rl, fmaf(M01, gl, M02 * bl));
    float Y = fmaf(M10, rl, fmaf(M11, gl, M12 * bl));
    float Z = fmaf(M20, rl, fmaf(M21, gl, M22 * bl));
    float fx = xyz_f(X);
    float fy = xyz_f(Y);
    float fz = xyz_f(Z);
    // L01 = (L - Lmin)/(Lmax - Lmin) = (fy - fmin) * sf,  sf = 1/(fmax - fmin)
    L01 = (fy - fmin) * sf;
    a01 = fmaf(fx - fy, 500.0f / 255.0f, 128.0f / 255.0f);
    b01 = fmaf(fy - fz, 200.0f / 255.0f, 128.0f / 255.0f);
}

__global__ void __launch_bounds__(THREADS)
convert_kernel(const float* __restrict__ x, float* __restrict__ out) {
    const int bid = blockIdx.x;                       // 0 .. NIMG*K2_SUBS-1
    const int img = (NIMG - 1) - (bid >> 3);          // reverse order for L2 reuse
    const int sub = bid & 7;
    const int tid = threadIdx.x;

    // reduce this image's 4 partials (Y domain), convert to f domain
    float ymn = fminf(fminf(g_pmin[img * 4 + 0], g_pmin[img * 4 + 1]),
                      fminf(g_pmin[img * 4 + 2], g_pmin[img * 4 + 3]));
    float ymx = fmaxf(fmaxf(g_pmax[img * 4 + 0], g_pmax[img * 4 + 1]),
                      fmaxf(g_pmax[img * 4 + 2], g_pmax[img * 4 + 3]));
    float fmin = xyz_f(ymn);
    float fmax = xyz_f(ymx);
    float sf = mufu_rcp(fmax - fmin);

    const float4* in4 = (const float4*)(x   + (size_t)img * NPIX * 3)
                      + (size_t)sub * (K2_PX * 3 / 4);
    float4*       o4  = (float4*)      (out + (size_t)img * NPIX * 3)
                      + (size_t)sub * (K2_PX * 3 / 4);

    #pragma unroll
    for (int j = 0; j < K2_GROUPS; j++) {
        int gi = tid + j * THREADS;             // group of 4 pixels
        float4 v0 = in4[(size_t)gi * 3 + 0];
        float4 v1 = in4[(size_t)gi * 3 + 1];
        float4 v2 = in4[(size_t)gi * 3 + 2];

        float L0, a0, b0, L1, a1, b1, L2, a2, b2, L3, a3, b3;
        lab_pixel(v0.x, v0.y, v0.z, fmin, sf, L0, a0, b0);
        lab_pixel(v0.w, v1.x, v1.y, fmin, sf, L1, a1, b1);
        lab_pixel(v1.z, v1.w, v2.x, fmin, sf, L2, a2, b2);
        lab_pixel(v2.y, v2.z, v2.w, fmin, sf, L3, a3, b3);

        o4[(size_t)gi * 3 + 0] = make_float4(L0, a0, b0, L1);
        o4[(size_t)gi * 3 + 1] = make_float4(a1, b1, L2, a2);
        o4[(size_t)gi * 3 + 2] = make_float4(b2, L3, a3, b3);
    }
}

extern "C" void kernel_launch(void* const* d_in, const int* in_sizes, int n_in,
                              void* d_out, int out_size) {
    const float* x   = (const float*)d_in[0];
    float*       out = (float*)d_out;

    minmax_kernel <<<NIMG * K1_SUBS, THREADS>>>(x);
    convert_kernel<<<NIMG * K2_SUBS, THREADS>>>(x, out);
}